// round 15
// baseline (speedup 1.0000x reference)
#include <cuda_runtime.h>
#include <cuda_fp16.h>
#include <math.h>
#include <stdint.h>

#define N_TOK 32768
#define F_IN  512
#define F_HID 2048
#define F_OUT 512

// ---------------- scratch (static device globals; no runtime alloc) ----------
__device__ float g_Y1[F_IN * F_HID];                    // solve(M1^T, W1^T)
__device__ float g_Y2[F_HID * F_OUT];
// tiled fp16 operands: [rowTile][kTile] of 16KB ([128 rows][64 k], swizzled)
__device__ __half g_W1[F_HID * F_IN];                   // 16 x 8 tiles
__device__ __half g_W2[F_OUT * F_HID];                  // 4 x 32 tiles
__device__ __half g_x16[(size_t)N_TOK * F_IN];          // 256 x 8 tiles
__device__ __half g_h16[(size_t)N_TOK * F_HID];         // 256 x 32 tiles

// ======================= helpers =======================
__device__ __forceinline__ uint32_t smem_u32(const void* p) {
    uint32_t a;
    asm("{ .reg .u64 t; cvta.to.shared.u64 t, %1; cvt.u32.u64 %0, t; }"
        : "=r"(a) : "l"(p));
    return a;
}
__device__ __forceinline__ void ldm_x4(uint32_t& r0, uint32_t& r1, uint32_t& r2,
                                       uint32_t& r3, uint32_t a) {
    asm volatile("ldmatrix.sync.aligned.m8n8.x4.shared.b16 {%0,%1,%2,%3}, [%4];"
        : "=r"(r0), "=r"(r1), "=r"(r2), "=r"(r3) : "r"(a));
}
__device__ __forceinline__ void mma_f16(float* c, const uint32_t* a,
                                        uint32_t b0, uint32_t b1) {
    asm volatile("mma.sync.aligned.m16n8k16.row.col.f32.f16.f16.f32 "
        "{%0,%1,%2,%3}, {%4,%5,%6,%7}, {%8,%9}, {%0,%1,%2,%3};"
        : "+f"(c[0]), "+f"(c[1]), "+f"(c[2]), "+f"(c[3])
        : "r"(a[0]), "r"(a[1]), "r"(a[2]), "r"(a[3]), "r"(b0), "r"(b1));
}
__device__ __forceinline__ uint32_t packh(__half a, __half b) {
    return (uint32_t)__half_as_ushort(a) | ((uint32_t)__half_as_ushort(b) << 16);
}
// canonical SW128 swizzle inside a [128 x 64] fp16 tile (128B rows)
__device__ __forceinline__ uint32_t swz(int r, int c16) {
    return (uint32_t)(r * 128 + ((c16 ^ (r & 7)) << 4));
}

#define MBAR_INIT(a, c) \
    asm volatile("mbarrier.init.shared.b64 [%0], %1;" :: "r"(a), "r"(c) : "memory")
#define MBAR_EXPECT_TX(a, b) \
    asm volatile("mbarrier.arrive.expect_tx.shared.b64 _, [%0], %1;" \
        :: "r"(a), "r"(b) : "memory")
#define MBAR_ARRIVE(a) \
    asm volatile("mbarrier.arrive.shared.b64 _, [%0];" :: "r"(a) : "memory")
#define MBAR_WAIT_PARITY(mbar_addr, parity) do {                                   \
    uint32_t _mb = (uint32_t)(mbar_addr);                                          \
    uint32_t _pa = (uint32_t)(parity);                                             \
    uint32_t _done;                                                                \
    asm volatile("{\n\t.reg .pred p;\n\t"                                          \
        "mbarrier.try_wait.parity.shared.b64 p, [%1], %2;\n\t"                     \
        "selp.b32 %0, 1, 0, p;\n\t}"                                               \
        : "=r"(_done) : "r"(_mb), "r"(_pa) : "memory");                            \
    while (!_done) {                                                               \
        asm volatile("{\n\t.reg .pred p;\n\t"                                      \
            "mbarrier.try_wait.parity.shared.b64 p, [%1], %2;\n\t"                 \
            "selp.b32 %0, 1, 0, p;\n\t}"                                           \
            : "=r"(_done) : "r"(_mb), "r"(_pa) : "memory");                        \
    }                                                                              \
} while (0)

__device__ __forceinline__ void bulk_g2s(uint32_t dst, const void* src,
                                         uint32_t mbar) {
    asm volatile(
        "cp.async.bulk.shared::cluster.global.mbarrier::complete_tx::bytes "
        "[%0], [%1], %2, [%3];"
        :: "r"(dst), "l"(src), "r"(16384u), "r"(mbar) : "memory");
}

// ======================= fused prep: factorize + solve + cast =============
// Blocks 0..15: layer-1 solve (n=512, 128 RHS each).
// Blocks 16..19: layer-2 solve (n=2048, 128 RHS each).
// Blocks 20.. : cast x fp32 -> tiled fp16 (2 chunks of 16B per thread).
// Factorization uses 3 parallel Jacobi substitutions of the continued
// fraction den_i = d_i - lo_i*up_{i-1}/den_{i-1} (diag dominance: |corr|
// contraction ~1e-5 per pass -> err ~1e-15 after 3).
#define CAST_BLK0 20

__global__ void __launch_bounds__(128) prep_all(
    const float* x4raw,
    const float* d1, const float* l1, const float* u1, const float* W1, float* Y1,
    const float* d2, const float* l2, const float* u2, const float* W2, float* Y2,
    char* xt) {
    int bid = blockIdx.x, t = threadIdx.x;

    if (bid >= CAST_BLK0) {
        // -------- cast x --------
        const float4* x4 = (const float4*)x4raw;
        int base = ((bid - CAST_BLK0) * 128 + t) * 2;
#pragma unroll
        for (int q = 0; q < 2; q++) {
            int i = base + q;                 // chunk index (16B of fp16 out)
            int row = i >> 6, ck = i & 63;
            float4 v0 = x4[2 * i], v1 = x4[2 * i + 1];
            uint4 o = make_uint4(
                packh(__float2half_rn(v0.x), __float2half_rn(v0.y)),
                packh(__float2half_rn(v0.z), __float2half_rn(v0.w)),
                packh(__float2half_rn(v1.x), __float2half_rn(v1.y)),
                packh(__float2half_rn(v1.z), __float2half_rn(v1.w)));
            uint32_t tile = (uint32_t)(row >> 7) * 8u + (ck >> 3);
            *(uint4*)(xt + tile * 16384u + swz(row & 127, ck & 7)) = o;
        }
        return;
    }

    // -------- factorize (parallel) + solve --------
    __shared__ float sd[2048], slo[2048], sup[2048], dA[2048], dB[2048];
    const float *d, *l, *u, *W; float* Y; int n, nrhs, j0;
    if (bid < 16) { d = d1; l = l1; u = u1; W = W1; Y = Y1;
                    n = F_IN;  nrhs = F_HID; j0 = bid * 128; }
    else          { d = d2; l = l2; u = u2; W = W2; Y = Y2;
                    n = F_HID; nrhs = F_OUT; j0 = (bid - 16) * 128; }

    for (int i = t; i < n; i += 128) {
        float di = d[i];
        float sp = (di > 20.f) ? di : log1pf(expf(di));
        sd[i]  = sp + 2.f;
        slo[i] = (i > 0)     ? tanhf(u[i - 1]) : 0.f;   // sub of M^T
        sup[i] = (i < n - 1) ? tanhf(l[i])     : 0.f;   // super of M^T
    }
    __syncthreads();
    // Jacobi pass 1: dA = d - lo*up'/d
    for (int i = t; i < n; i += 128)
        dA[i] = (i > 0) ? sd[i] - slo[i] * sup[i - 1] / sd[i - 1] : sd[i];
    __syncthreads();
    // pass 2: dB from dA
    for (int i = t; i < n; i += 128)
        dB[i] = (i > 0) ? sd[i] - slo[i] * sup[i - 1] / dA[i - 1] : sd[i];
    __syncthreads();
    // pass 3: dA from dB, then rd = 1/den into sd
    for (int i = t; i < n; i += 128)
        dA[i] = (i > 0) ? sd[i] - slo[i] * sup[i - 1] / dB[i - 1] : sd[i];
    __syncthreads();
    for (int i = t; i < n; i += 128)
        sd[i] = 1.f / dA[i];                 // sd := reciprocal denominators
    __syncthreads();
    for (int i = t; i < n; i += 128)
        sup[i] = sup[i] * sd[i];             // sup := modified upper (cp)
    __syncthreads();

    // Thomas solve, one RHS column per thread (smem-resident coefficients)
    int j = j0 + t;
    const float* r = W + (size_t)j * n;
    float z = r[0] * sd[0];
    Y[j] = z;
#pragma unroll 4
    for (int i = 1; i < n; i++) {
        z = (r[i] - slo[i] * z) * sd[i];
        Y[(size_t)i * nrhs + j] = z;
    }
    float y = z;
#pragma unroll 4
    for (int i = n - 2; i >= 0; i--) {
        y = Y[(size_t)i * nrhs + j] - sup[i] * y;
        Y[(size_t)i * nrhs + j] = y;
    }
}

// transpose [K][Nr] fp32 -> tiled fp16 [Nr-tiles][K-tiles][128x64 swizzled]
__global__ void trans_f16(const float* __restrict__ in, char* __restrict__ out,
                          int Kd, int C) {   // in: [Kd][C]; out rows = C (N-dim)
    __shared__ float t[32][33];
    int c0 = blockIdx.x * 32, r0 = blockIdx.y * 32;
    int x = threadIdx.x, y = threadIdx.y;
#pragma unroll
    for (int i = 0; i < 32; i += 8)
        t[y + i][x] = in[(size_t)(r0 + y + i) * C + c0 + x];
    __syncthreads();
    const int kt = Kd >> 6;
#pragma unroll
    for (int i = 0; i < 32; i += 8) {
        int nrow = c0 + y + i;     // N dimension
        int kcol = r0 + x;         // K dimension
        uint32_t tile = (uint32_t)(nrow >> 7) * kt + (kcol >> 6);
        uint32_t off = tile * 16384u + swz(nrow & 127, (kcol >> 3) & 7)
                     + (uint32_t)(kcol & 7) * 2u;
        *(__half*)(out + off) = __float2half_rn(t[x][y + i]);
    }
}

// ======================= fp16 mma.sync GEMM (R14 verbatim) ================
#define TILE_A  16384u
#define STG_BYTES 32768u
#define MBAR_OFF (3u * STG_BYTES)
#define GEMM_SMEM (3 * 32768 + 64)

template <bool FUSE>   // FUSE: relu + tiled fp16 out (Ch); else fp32 out (Cf)
__global__ void __launch_bounds__(256, 2) gemm_f16(
    const char* __restrict__ At, const char* __restrict__ Bt,
    const float* __restrict__ bias, float* __restrict__ Cf,
    char* __restrict__ Ch, int N, int K) {
    extern __shared__ char smem[];
    uint32_t sb = smem_u32(smem);
    const int tid = threadIdx.x;
    const int lane = tid & 31, wid = tid >> 5;
    const int wm = wid & 3, wn = wid >> 2;       // warp tile 32(m) x 64(n)
    const int rowB = blockIdx.y * 128, colB = blockIdx.x * 128;
    const int kt = K >> 6;                       // 64-K stages
    const char* Abase = At + (size_t)blockIdx.y * kt * 16384u;
    const char* Bbase = Bt + (size_t)blockIdx.x * kt * 16384u;
    const uint32_t mbF = sb + MBAR_OFF;          // full[0..2]  at +0,+8,+16
    const uint32_t mbE = sb + MBAR_OFF + 24u;    // empty[0..2] at +24,+32,+40

    float acc[2][8][4] = {};

    if (tid == 0) {
#pragma unroll
        for (int b = 0; b < 3; b++) {
            MBAR_INIT(mbF + 8u * b, 1);
            MBAR_INIT(mbE + 8u * b, 256);
        }
    }
    __syncthreads();

    if (tid == 0) {
#pragma unroll
        for (int s = 0; s < 2; s++) {
            MBAR_EXPECT_TX(mbF + 8u * s, 32768u);
            bulk_g2s(sb + s * STG_BYTES,           Abase + (size_t)s * 16384u, mbF + 8u * s);
            bulk_g2s(sb + s * STG_BYTES + TILE_A,  Bbase + (size_t)s * 16384u, mbF + 8u * s);
        }
    }

    const int lr = lane & 15, kh = lane >> 4;
    const int lg = lane >> 2, lt = lane & 3;
    const int rA0 = wm * 32 + lr, rA1 = wm * 32 + 16 + lr;
    const int rB0 = wn * 64 + lr;

    for (int s = 0; s < kt; s++) {
        const int b = s % 3;

        if (tid == 0) {
            int pf = s + 2;
            if (pf < kt) {
                int pb = pf % 3;
                if (pf >= 3)
                    MBAR_WAIT_PARITY(mbE + 8u * pb, ((pf / 3) - 1) & 1);
                MBAR_EXPECT_TX(mbF + 8u * pb, 32768u);
                bulk_g2s(sb + pb * STG_BYTES,          Abase + (size_t)pf * 16384u, mbF + 8u * pb);
                bulk_g2s(sb + pb * STG_BYTES + TILE_A, Bbase + (size_t)pf * 16384u, mbF + 8u * pb);
            }
        }

        MBAR_WAIT_PARITY(mbF + 8u * b, (s / 3) & 1);

        uint32_t sA = sb + (uint32_t)b * STG_BYTES;
        uint32_t sBs = sA + TILE_A;

        uint32_t afr[2][2][4];
        uint32_t bfr[2][4];
        ldm_x4(afr[0][0][0], afr[0][0][1], afr[0][0][2], afr[0][0][3],
               sA + swz(rA0, kh));
        ldm_x4(afr[0][1][0], afr[0][1][1], afr[0][1][2], afr[0][1][3],
               sA + swz(rA1, kh));
        ldm_x4(bfr[0][0], bfr[0][1], bfr[0][2], bfr[0][3],
               sBs + swz(rB0, kh));

#pragma unroll
        for (int kk = 0; kk < 4; kk++) {
            const int ca = kk & 1;
            if (kk < 3) {
                ldm_x4(afr[ca ^ 1][0][0], afr[ca ^ 1][0][1],
                       afr[ca ^ 1][0][2], afr[ca ^ 1][0][3],
                       sA + swz(rA0, 2 * (kk + 1) + kh));
                ldm_x4(afr[ca ^ 1][1][0], afr[ca ^ 1][1][1],
                       afr[ca ^ 1][1][2], afr[ca ^ 1][1][3],
                       sA + swz(rA1, 2 * (kk + 1) + kh));
            }
#pragma unroll
            for (int pt = 0; pt < 4; pt++) {
                const int cb = (kk * 4 + pt) & 1;
                if (pt < 3)
                    ldm_x4(bfr[cb ^ 1][0], bfr[cb ^ 1][1],
                           bfr[cb ^ 1][2], bfr[cb ^ 1][3],
                           sBs + swz(rB0 + (pt + 1) * 16, 2 * kk + kh));
                else if (kk < 3)
                    ldm_x4(bfr[cb ^ 1][0], bfr[cb ^ 1][1],
                           bfr[cb ^ 1][2], bfr[cb ^ 1][3],
                           sBs + swz(rB0, 2 * (kk + 1) + kh));
#pragma unroll
                for (int mt = 0; mt < 2; mt++) {
                    mma_f16(acc[mt][2 * pt],     afr[ca][mt], bfr[cb][0], bfr[cb][2]);
                    mma_f16(acc[mt][2 * pt + 1], afr[ca][mt], bfr[cb][1], bfr[cb][3]);
                }
            }
        }
        MBAR_ARRIVE(mbE + 8u * b);   // this thread is done reading buffer b
    }

    // epilogue
    const int ktC = N >> 6;   // k-tiles of the OUTPUT when FUSE (h tiled layout)
#pragma unroll
    for (int mt = 0; mt < 2; mt++) {
        int r0 = rowB + wm * 32 + mt * 16 + lg;
#pragma unroll
        for (int n8 = 0; n8 < 8; n8++) {
            int c = colB + wn * 64 + n8 * 8 + 2 * lt;
            float b0v = bias[c], b1v = bias[c + 1];
            float v0 = acc[mt][n8][0] + b0v;
            float v1 = acc[mt][n8][1] + b1v;
            float v2 = acc[mt][n8][2] + b0v;
            float v3 = acc[mt][n8][3] + b1v;
            if (FUSE) {
                v0 = fmaxf(v0, 0.f); v1 = fmaxf(v1, 0.f);
                v2 = fmaxf(v2, 0.f); v3 = fmaxf(v3, 0.f);
                uint32_t tile = (uint32_t)(r0 >> 7) * ktC + (c >> 6);
                uint32_t base = tile * 16384u + (uint32_t)(c & 7) * 2u;
                *(uint32_t*)(Ch + base + swz(r0 & 127, (c >> 3) & 7)) =
                    packh(__float2half_rn(v0), __float2half_rn(v1));
                *(uint32_t*)(Ch + base + swz((r0 + 8) & 127, (c >> 3) & 7)) =
                    packh(__float2half_rn(v2), __float2half_rn(v3));
            } else {
                *(float2*)(Cf + (size_t)r0 * N + c)       = make_float2(v0, v1);
                *(float2*)(Cf + (size_t)(r0 + 8) * N + c) = make_float2(v2, v3);
            }
        }
    }
}

// ======================= launch =======================
extern "C" void kernel_launch(void* const* d_in, const int* in_sizes, int n_in,
                              void* d_out, int out_size) {
    const float* x  = (const float*)d_in[0];
    const float* d1 = (const float*)d_in[1];
    const float* l1 = (const float*)d_in[2];
    const float* u1 = (const float*)d_in[3];
    const float* W1 = (const float*)d_in[4];
    const float* b1 = (const float*)d_in[5];
    const float* d2 = (const float*)d_in[6];
    const float* l2 = (const float*)d_in[7];
    const float* u2 = (const float*)d_in[8];
    const float* W2 = (const float*)d_in[9];
    const float* b2 = (const float*)d_in[10];
    float* out = (float*)d_out;

    float *Y1, *Y2;
    __half *W1f, *W2f, *x16, *h16;
    cudaGetSymbolAddress((void**)&Y1,  g_Y1);
    cudaGetSymbolAddress((void**)&Y2,  g_Y2);
    cudaGetSymbolAddress((void**)&W1f, g_W1);
    cudaGetSymbolAddress((void**)&W2f, g_W2);
    cudaGetSymbolAddress((void**)&x16, g_x16);
    cudaGetSymbolAddress((void**)&h16, g_h16);

    cudaFuncSetAttribute(gemm_f16<true>,
                         cudaFuncAttributeMaxDynamicSharedMemorySize, GEMM_SMEM);
    cudaFuncSetAttribute(gemm_f16<false>,
                         cudaFuncAttributeMaxDynamicSharedMemorySize, GEMM_SMEM);

    // 1) fused prep: factorize+solve (blocks 0..19) || cast x (blocks 20..)
    {
        int cast_blocks = (N_TOK * F_IN / 8) / (128 * 2);   // 8192
        prep_all<<<CAST_BLK0 + cast_blocks, 128>>>(
            x, d1, l1, u1, W1, Y1, d2, l2, u2, W2, Y2, (char*)x16);
    }
    // 2) transpose folded weights to tiled fp16
    trans_f16<<<dim3(F_HID / 32, F_IN / 32),  dim3(32, 8)>>>(Y1, (char*)W1f, F_IN,  F_HID);
    trans_f16<<<dim3(F_OUT / 32, F_HID / 32), dim3(32, 8)>>>(Y2, (char*)W2f, F_HID, F_OUT);
    // 3) h = relu(x @ W1p^T + b1) -> tiled fp16
    gemm_f16<true><<<dim3(F_HID / 128, N_TOK / 128), 256, GEMM_SMEM>>>(
        (const char*)x16, (const char*)W1f, b1, nullptr, (char*)h16, F_HID, F_IN);
    // 4) out = h @ W2p^T + b2 -> fp32
    gemm_f16<false><<<dim3(F_OUT / 128, N_TOK / 128), 256, GEMM_SMEM>>>(
        (const char*)h16, (const char*)W2f, b2, out, nullptr, F_OUT, F_HID);
}

// round 16
// speedup vs baseline: 1.1156x; 1.1156x over previous
#include <cuda_runtime.h>
#include <cuda_fp16.h>
#include <math.h>
#include <stdint.h>

#define N_TOK 32768
#define F_IN  512
#define F_HID 2048
#define F_OUT 512

// ---------------- scratch (static device globals; no runtime alloc) ----------
__device__ float g_lo1[F_IN],  g_cp1[F_IN],  g_rd1[F_IN];
__device__ float g_lo2[F_HID], g_cp2[F_HID], g_rd2[F_HID];
__device__ float g_W1t[F_IN * F_HID];                   // W1^T  [512][2048]
__device__ float g_W2t[F_HID * F_OUT];                  // W2^T  [2048][512]
__device__ float g_Y1[F_IN * F_HID];                    // solve(M1^T, W1^T)
__device__ float g_Y2[F_HID * F_OUT];
// tiled fp16 operands: [rowTile][kTile] of 16KB ([128 rows][64 k], swizzled)
__device__ __half g_W1[F_HID * F_IN];                   // 16 x 8 tiles
__device__ __half g_W2[F_OUT * F_HID];                  // 4 x 32 tiles
__device__ __half g_x16[(size_t)N_TOK * F_IN];          // 256 x 8 tiles
__device__ __half g_h16[(size_t)N_TOK * F_HID];         // 256 x 32 tiles

// ======================= helpers =======================
__device__ __forceinline__ uint32_t smem_u32(const void* p) {
    uint32_t a;
    asm("{ .reg .u64 t; cvta.to.shared.u64 t, %1; cvt.u32.u64 %0, t; }"
        : "=r"(a) : "l"(p));
    return a;
}
__device__ __forceinline__ void ldm_x4(uint32_t& r0, uint32_t& r1, uint32_t& r2,
                                       uint32_t& r3, uint32_t a) {
    asm volatile("ldmatrix.sync.aligned.m8n8.x4.shared.b16 {%0,%1,%2,%3}, [%4];"
        : "=r"(r0), "=r"(r1), "=r"(r2), "=r"(r3) : "r"(a));
}
__device__ __forceinline__ void mma_f16(float* c, const uint32_t* a,
                                        uint32_t b0, uint32_t b1) {
    asm volatile("mma.sync.aligned.m16n8k16.row.col.f32.f16.f16.f32 "
        "{%0,%1,%2,%3}, {%4,%5,%6,%7}, {%8,%9}, {%0,%1,%2,%3};"
        : "+f"(c[0]), "+f"(c[1]), "+f"(c[2]), "+f"(c[3])
        : "r"(a[0]), "r"(a[1]), "r"(a[2]), "r"(a[3]), "r"(b0), "r"(b1));
}
__device__ __forceinline__ uint32_t packh(__half a, __half b) {
    return (uint32_t)__half_as_ushort(a) | ((uint32_t)__half_as_ushort(b) << 16);
}
// canonical SW128 swizzle inside a [128 x 64] fp16 tile (128B rows)
__device__ __forceinline__ uint32_t swz(int r, int c16) {
    return (uint32_t)(r * 128 + ((c16 ^ (r & 7)) << 4));
}

#define MBAR_INIT(a, c) \
    asm volatile("mbarrier.init.shared.b64 [%0], %1;" :: "r"(a), "r"(c) : "memory")
#define MBAR_EXPECT_TX(a, b) \
    asm volatile("mbarrier.arrive.expect_tx.shared.b64 _, [%0], %1;" \
        :: "r"(a), "r"(b) : "memory")
#define MBAR_ARRIVE(a) \
    asm volatile("mbarrier.arrive.shared.b64 _, [%0];" :: "r"(a) : "memory")
#define MBAR_WAIT_PARITY(mbar_addr, parity) do {                                   \
    uint32_t _mb = (uint32_t)(mbar_addr);                                          \
    uint32_t _pa = (uint32_t)(parity);                                             \
    uint32_t _done;                                                                \
    asm volatile("{\n\t.reg .pred p;\n\t"                                          \
        "mbarrier.try_wait.parity.shared.b64 p, [%1], %2;\n\t"                     \
        "selp.b32 %0, 1, 0, p;\n\t}"                                               \
        : "=r"(_done) : "r"(_mb), "r"(_pa) : "memory");                            \
    while (!_done) {                                                               \
        asm volatile("{\n\t.reg .pred p;\n\t"                                      \
            "mbarrier.try_wait.parity.shared.b64 p, [%1], %2;\n\t"                 \
            "selp.b32 %0, 1, 0, p;\n\t}"                                           \
            : "=r"(_done) : "r"(_mb), "r"(_pa) : "memory");                        \
    }                                                                              \
} while (0)

__device__ __forceinline__ void bulk_g2s(uint32_t dst, const void* src,
                                         uint32_t mbar) {
    asm volatile(
        "cp.async.bulk.shared::cluster.global.mbarrier::complete_tx::bytes "
        "[%0], [%1], %2, [%3];"
        :: "r"(dst), "l"(src), "r"(16384u), "r"(mbar) : "memory");
}

// ======================= prep kernels =======================
__global__ void prep_both(const float* d1, const float* l1, const float* u1,
                          const float* d2, const float* l2, const float* u2,
                          float* lo1, float* cp1, float* rd1,
                          float* lo2, float* cp2, float* rd2) {
    __shared__ float sd[2048], slo[2048], sup[2048];
    const float *d, *l, *u; float *lo, *cp, *rd; int n;
    if (blockIdx.x == 0) { d = d1; l = l1; u = u1; lo = lo1; cp = cp1; rd = rd1; n = F_IN; }
    else                 { d = d2; l = l2; u = u2; lo = lo2; cp = cp2; rd = rd2; n = F_HID; }
    int t = threadIdx.x;
    for (int i = t; i < n; i += blockDim.x) {
        float di = d[i];
        float sp = (di > 20.f) ? di : log1pf(expf(di));
        sd[i]  = sp + 2.f;
        slo[i] = (i > 0)     ? tanhf(u[i - 1]) : 0.f;   // sub of M^T
        sup[i] = (i < n - 1) ? tanhf(l[i])     : 0.f;   // super of M^T
    }
    __syncthreads();
    if (t == 0) {
        float cprev = 0.f;
        for (int i = 0; i < n; i++) {
            float den = sd[i] - slo[i] * cprev;
            float r = 1.f / den;
            sd[i] = r;
            cprev = sup[i] * r;
            sup[i] = cprev;
        }
    }
    __syncthreads();
    for (int i = t; i < n; i += blockDim.x) {
        rd[i] = sd[i]; cp[i] = sup[i]; lo[i] = slo[i];
    }
}

// fp32 transpose: in [R][C] -> out [C][R]
__global__ void trans32(const float* __restrict__ in, float* __restrict__ out,
                        int R, int C) {
    __shared__ float t[32][33];
    int c0 = blockIdx.x * 32, r0 = blockIdx.y * 32;
    int x = threadIdx.x, y = threadIdx.y;
#pragma unroll
    for (int i = 0; i < 32; i += 8)
        t[y + i][x] = in[(size_t)(r0 + y + i) * C + c0 + x];
    __syncthreads();
#pragma unroll
    for (int i = 0; i < 32; i += 8)
        out[(size_t)(c0 + y + i) * R + r0 + x] = t[x][y + i];
}

// Thomas solve, coalesced RHS-major reads, single-FMA chains.
// Rt: [n][nrhs] (transposed weights). Y: [n][nrhs]. 1 thread / RHS column.
// blocks 0..15: layer 1 (n=512, nrhs=2048); 16..19: layer 2 (n=2048, nrhs=512)
__global__ void __launch_bounds__(128) solve_both(
    const float* lo1, const float* cp1, const float* rd1,
    const float* __restrict__ W1t, float* __restrict__ Y1,
    const float* lo2, const float* cp2, const float* rd2,
    const float* __restrict__ W2t, float* __restrict__ Y2) {
    __shared__ float sa[2048], srd[2048], scp[2048];
    int bid = blockIdx.x, t = threadIdx.x;
    const float *lo, *cp, *rd, *Rt; float* Y; int n, nrhs, j;
    if (bid < 16) { lo = lo1; cp = cp1; rd = rd1; Rt = W1t; Y = Y1;
                    n = F_IN;  nrhs = F_HID; j = bid * 128 + t; }
    else          { lo = lo2; cp = cp2; rd = rd2; Rt = W2t; Y = Y2;
                    n = F_HID; nrhs = F_OUT; j = (bid - 16) * 128 + t; }
    for (int i = t; i < n; i += 128) {
        float r = rd[i];
        srd[i] = r;
        sa[i]  = lo[i] * r;     // fused forward coefficient
        scp[i] = cp[i];
    }
    __syncthreads();

    // forward: z_i = rd_i*r_i - (lo_i*rd_i)*z_{i-1}
    float z = Rt[j] * srd[0];
    Y[j] = z;
#pragma unroll 8
    for (int i = 1; i < n; i++) {
        float b = Rt[(size_t)i * nrhs + j] * srd[i];
        z = fmaf(-sa[i], z, b);
        Y[(size_t)i * nrhs + j] = z;
    }
    // backward: y_i = Y_i - cp_i*y_{i+1}
    float y = z;
#pragma unroll 8
    for (int i = n - 2; i >= 0; i--) {
        float v = Y[(size_t)i * nrhs + j];
        y = fmaf(-scp[i], y, v);
        Y[(size_t)i * nrhs + j] = y;
    }
}

// transpose [K][Nr] fp32 -> tiled fp16 [Nr-tiles][K-tiles][128x64 swizzled]
__global__ void trans_f16(const float* __restrict__ in, char* __restrict__ out,
                          int Kd, int C) {   // in: [Kd][C]; out rows = C (N-dim)
    __shared__ float t[32][33];
    int c0 = blockIdx.x * 32, r0 = blockIdx.y * 32;
    int x = threadIdx.x, y = threadIdx.y;
#pragma unroll
    for (int i = 0; i < 32; i += 8)
        t[y + i][x] = in[(size_t)(r0 + y + i) * C + c0 + x];
    __syncthreads();
    const int kt = Kd >> 6;
#pragma unroll
    for (int i = 0; i < 32; i += 8) {
        int nrow = c0 + y + i;     // N dimension
        int kcol = r0 + x;         // K dimension
        uint32_t tile = (uint32_t)(nrow >> 7) * kt + (kcol >> 6);
        uint32_t off = tile * 16384u + swz(nrow & 127, (kcol >> 3) & 7)
                     + (uint32_t)(kcol & 7) * 2u;
        *(__half*)(out + off) = __float2half_rn(t[x][y + i]);
    }
}

// cast x fp32 -> tiled fp16 (8 floats -> one 16B swizzled chunk per thread)
__global__ void cast_f16(const float4* __restrict__ x, char* __restrict__ xt,
                         int n8) {
    int i = blockIdx.x * blockDim.x + threadIdx.x;
    if (i >= n8) return;
    int row = i >> 6;              // 64 chunks per 512-wide row
    int ck  = i & 63;
    float4 v0 = x[2 * i], v1 = x[2 * i + 1];
    uint4 o = make_uint4(packh(__float2half_rn(v0.x), __float2half_rn(v0.y)),
                         packh(__float2half_rn(v0.z), __float2half_rn(v0.w)),
                         packh(__float2half_rn(v1.x), __float2half_rn(v1.y)),
                         packh(__float2half_rn(v1.z), __float2half_rn(v1.w)));
    uint32_t tile = (uint32_t)(row >> 7) * 8u + (ck >> 3);
    *(uint4*)(xt + tile * 16384u + swz(row & 127, ck & 7)) = o;
}

// ======================= fp16 mma.sync GEMM (R14 verbatim) ================
#define TILE_A  16384u
#define STG_BYTES 32768u
#define MBAR_OFF (3u * STG_BYTES)
#define GEMM_SMEM (3 * 32768 + 64)

template <bool FUSE>   // FUSE: relu + tiled fp16 out (Ch); else fp32 out (Cf)
__global__ void __launch_bounds__(256, 2) gemm_f16(
    const char* __restrict__ At, const char* __restrict__ Bt,
    const float* __restrict__ bias, float* __restrict__ Cf,
    char* __restrict__ Ch, int N, int K) {
    extern __shared__ char smem[];
    uint32_t sb = smem_u32(smem);
    const int tid = threadIdx.x;
    const int lane = tid & 31, wid = tid >> 5;
    const int wm = wid & 3, wn = wid >> 2;       // warp tile 32(m) x 64(n)
    const int rowB = blockIdx.y * 128, colB = blockIdx.x * 128;
    const int kt = K >> 6;                       // 64-K stages
    const char* Abase = At + (size_t)blockIdx.y * kt * 16384u;
    const char* Bbase = Bt + (size_t)blockIdx.x * kt * 16384u;
    const uint32_t mbF = sb + MBAR_OFF;          // full[0..2]  at +0,+8,+16
    const uint32_t mbE = sb + MBAR_OFF + 24u;    // empty[0..2] at +24,+32,+40

    float acc[2][8][4] = {};

    if (tid == 0) {
#pragma unroll
        for (int b = 0; b < 3; b++) {
            MBAR_INIT(mbF + 8u * b, 1);
            MBAR_INIT(mbE + 8u * b, 256);
        }
    }
    __syncthreads();

    if (tid == 0) {
#pragma unroll
        for (int s = 0; s < 2; s++) {
            MBAR_EXPECT_TX(mbF + 8u * s, 32768u);
            bulk_g2s(sb + s * STG_BYTES,           Abase + (size_t)s * 16384u, mbF + 8u * s);
            bulk_g2s(sb + s * STG_BYTES + TILE_A,  Bbase + (size_t)s * 16384u, mbF + 8u * s);
        }
    }

    const int lr = lane & 15, kh = lane >> 4;
    const int lg = lane >> 2, lt = lane & 3;
    const int rA0 = wm * 32 + lr, rA1 = wm * 32 + 16 + lr;
    const int rB0 = wn * 64 + lr;

    for (int s = 0; s < kt; s++) {
        const int b = s % 3;

        if (tid == 0) {
            int pf = s + 2;
            if (pf < kt) {
                int pb = pf % 3;
                if (pf >= 3)
                    MBAR_WAIT_PARITY(mbE + 8u * pb, ((pf / 3) - 1) & 1);
                MBAR_EXPECT_TX(mbF + 8u * pb, 32768u);
                bulk_g2s(sb + pb * STG_BYTES,          Abase + (size_t)pf * 16384u, mbF + 8u * pb);
                bulk_g2s(sb + pb * STG_BYTES + TILE_A, Bbase + (size_t)pf * 16384u, mbF + 8u * pb);
            }
        }

        MBAR_WAIT_PARITY(mbF + 8u * b, (s / 3) & 1);

        uint32_t sA = sb + (uint32_t)b * STG_BYTES;
        uint32_t sBs = sA + TILE_A;

        uint32_t afr[2][2][4];
        uint32_t bfr[2][4];
        ldm_x4(afr[0][0][0], afr[0][0][1], afr[0][0][2], afr[0][0][3],
               sA + swz(rA0, kh));
        ldm_x4(afr[0][1][0], afr[0][1][1], afr[0][1][2], afr[0][1][3],
               sA + swz(rA1, kh));
        ldm_x4(bfr[0][0], bfr[0][1], bfr[0][2], bfr[0][3],
               sBs + swz(rB0, kh));

#pragma unroll
        for (int kk = 0; kk < 4; kk++) {
            const int ca = kk & 1;
            if (kk < 3) {
                ldm_x4(afr[ca ^ 1][0][0], afr[ca ^ 1][0][1],
                       afr[ca ^ 1][0][2], afr[ca ^ 1][0][3],
                       sA + swz(rA0, 2 * (kk + 1) + kh));
                ldm_x4(afr[ca ^ 1][1][0], afr[ca ^ 1][1][1],
                       afr[ca ^ 1][1][2], afr[ca ^ 1][1][3],
                       sA + swz(rA1, 2 * (kk + 1) + kh));
            }
#pragma unroll
            for (int pt = 0; pt < 4; pt++) {
                const int cb = (kk * 4 + pt) & 1;
                if (pt < 3)
                    ldm_x4(bfr[cb ^ 1][0], bfr[cb ^ 1][1],
                           bfr[cb ^ 1][2], bfr[cb ^ 1][3],
                           sBs + swz(rB0 + (pt + 1) * 16, 2 * kk + kh));
                else if (kk < 3)
                    ldm_x4(bfr[cb ^ 1][0], bfr[cb ^ 1][1],
                           bfr[cb ^ 1][2], bfr[cb ^ 1][3],
                           sBs + swz(rB0, 2 * (kk + 1) + kh));
#pragma unroll
                for (int mt = 0; mt < 2; mt++) {
                    mma_f16(acc[mt][2 * pt],     afr[ca][mt], bfr[cb][0], bfr[cb][2]);
                    mma_f16(acc[mt][2 * pt + 1], afr[ca][mt], bfr[cb][1], bfr[cb][3]);
                }
            }
        }
        MBAR_ARRIVE(mbE + 8u * b);   // this thread is done reading buffer b
    }

    // epilogue
    const int ktC = N >> 6;   // k-tiles of the OUTPUT when FUSE (h tiled layout)
#pragma unroll
    for (int mt = 0; mt < 2; mt++) {
        int r0 = rowB + wm * 32 + mt * 16 + lg;
#pragma unroll
        for (int n8 = 0; n8 < 8; n8++) {
            int c = colB + wn * 64 + n8 * 8 + 2 * lt;
            float b0v = bias[c], b1v = bias[c + 1];
            float v0 = acc[mt][n8][0] + b0v;
            float v1 = acc[mt][n8][1] + b1v;
            float v2 = acc[mt][n8][2] + b0v;
            float v3 = acc[mt][n8][3] + b1v;
            if (FUSE) {
                v0 = fmaxf(v0, 0.f); v1 = fmaxf(v1, 0.f);
                v2 = fmaxf(v2, 0.f); v3 = fmaxf(v3, 0.f);
                uint32_t tile = (uint32_t)(r0 >> 7) * ktC + (c >> 6);
                uint32_t base = tile * 16384u + (uint32_t)(c & 7) * 2u;
                *(uint32_t*)(Ch + base + swz(r0 & 127, (c >> 3) & 7)) =
                    packh(__float2half_rn(v0), __float2half_rn(v1));
                *(uint32_t*)(Ch + base + swz((r0 + 8) & 127, (c >> 3) & 7)) =
                    packh(__float2half_rn(v2), __float2half_rn(v3));
            } else {
                *(float2*)(Cf + (size_t)r0 * N + c)       = make_float2(v0, v1);
                *(float2*)(Cf + (size_t)(r0 + 8) * N + c) = make_float2(v2, v3);
            }
        }
    }
}

// ======================= launch =======================
extern "C" void kernel_launch(void* const* d_in, const int* in_sizes, int n_in,
                              void* d_out, int out_size) {
    const float* x  = (const float*)d_in[0];
    const float* d1 = (const float*)d_in[1];
    const float* l1 = (const float*)d_in[2];
    const float* u1 = (const float*)d_in[3];
    const float* W1 = (const float*)d_in[4];
    const float* b1 = (const float*)d_in[5];
    const float* d2 = (const float*)d_in[6];
    const float* l2 = (const float*)d_in[7];
    const float* u2 = (const float*)d_in[8];
    const float* W2 = (const float*)d_in[9];
    const float* b2 = (const float*)d_in[10];
    float* out = (float*)d_out;

    float *lo1, *cp1, *rd1, *lo2, *cp2, *rd2, *W1t, *W2t, *Y1, *Y2;
    __half *W1f, *W2f, *x16, *h16;
    cudaGetSymbolAddress((void**)&lo1, g_lo1);
    cudaGetSymbolAddress((void**)&cp1, g_cp1);
    cudaGetSymbolAddress((void**)&rd1, g_rd1);
    cudaGetSymbolAddress((void**)&lo2, g_lo2);
    cudaGetSymbolAddress((void**)&cp2, g_cp2);
    cudaGetSymbolAddress((void**)&rd2, g_rd2);
    cudaGetSymbolAddress((void**)&W1t, g_W1t);
    cudaGetSymbolAddress((void**)&W2t, g_W2t);
    cudaGetSymbolAddress((void**)&Y1,  g_Y1);
    cudaGetSymbolAddress((void**)&Y2,  g_Y2);
    cudaGetSymbolAddress((void**)&W1f, g_W1);
    cudaGetSymbolAddress((void**)&W2f, g_W2);
    cudaGetSymbolAddress((void**)&x16, g_x16);
    cudaGetSymbolAddress((void**)&h16, g_h16);

    cudaFuncSetAttribute(gemm_f16<true>,
                         cudaFuncAttributeMaxDynamicSharedMemorySize, GEMM_SMEM);
    cudaFuncSetAttribute(gemm_f16<false>,
                         cudaFuncAttributeMaxDynamicSharedMemorySize, GEMM_SMEM);

    // 0) cast x to tiled fp16 (independent)
    {
        int n8 = (N_TOK * F_IN) / 8;
        cast_f16<<<(n8 + 255) / 256, 256>>>((const float4*)x, (char*)x16, n8);
    }
    // 1) factorize M1^T, M2^T
    prep_both<<<2, 256>>>(d1, l1, u1, d2, l2, u2, lo1, cp1, rd1, lo2, cp2, rd2);
    // 2) transpose weights (coalesced solve reads)
    trans32<<<dim3(F_IN / 32,  F_HID / 32), dim3(32, 8)>>>(W1, W1t, F_HID, F_IN);
    trans32<<<dim3(F_HID / 32, F_OUT / 32), dim3(32, 8)>>>(W2, W2t, F_OUT, F_HID);
    // 3) fold tridiag solves into weights (coalesced, FMA-chain)
    solve_both<<<20, 128>>>(lo1, cp1, rd1, W1t, Y1, lo2, cp2, rd2, W2t, Y2);
    // 4) transpose folded weights to tiled fp16
    trans_f16<<<dim3(F_HID / 32, F_IN / 32),  dim3(32, 8)>>>(Y1, (char*)W1f, F_IN,  F_HID);
    trans_f16<<<dim3(F_OUT / 32, F_HID / 32), dim3(32, 8)>>>(Y2, (char*)W2f, F_HID, F_OUT);
    // 5) h = relu(x @ W1p^T + b1) -> tiled fp16
    gemm_f16<true><<<dim3(F_HID / 128, N_TOK / 128), 256, GEMM_SMEM>>>(
        (const char*)x16, (const char*)W1f, b1, nullptr, (char*)h16, F_HID, F_IN);
    // 6) out = h @ W2p^T + b2 -> fp32
    gemm_f16<false><<<dim3(F_OUT / 128, N_TOK / 128), 256, GEMM_SMEM>>>(
        (const char*)h16, (const char*)W2f, b2, out, nullptr, F_OUT, F_HID);
}